// round 17
// baseline (speedup 1.0000x reference)
#include <cuda_runtime.h>
#include <cuda_fp16.h>
#include <cstdint>
#include <cstddef>

// ============================================================================
// TT-Linear, fp16 HMMA, fused, REGISTER-CHAINED z (R16).
//
//   stage1: z_b[m̂=512][i34=64] = G01(512x64) @ x_b^T   (K=64)   -> REGISTERS
//   stage2: y_b[o12=64][o34=64] = ẑ_b @ G23(512x64) + bias (K=512)
//   m̂ = r2*64 + o12. Warp (c2,nh,r2p) computes exactly the z fragments it
//   consumes in stage2 (Rb=2c2+mt, ks2=r2*4+nq): z never touches SMEM.
//   Stage2 partials (8 per output, over nh x r2p) reduced via a 64KB SMEM
//   tree (2 syncs) in the space the old sZ buffer occupied.
//
// SMEM: G01 64K + G23 64K + sRed 64K + sX 8K + sxf 17K = 217KB.
// ============================================================================

//  g_A : [mrb=32][ks=4][lane=32][4 words: a0,a1,a2,a3]           (fp16x2)
//  g_B : [ks=32][nbp=4][lane=32][4 words: nb0{b0,b1}, nb1{b0,b1}]
__device__ __align__(16) uint32_t g_A[16384];
__device__ __align__(16) uint32_t g_B[16384];

// ---------------------------------------------------------------- helpers
__device__ __forceinline__ uint32_t pack_h2(float a, float b) {
    uint32_t r;
    asm("cvt.rn.f16x2.f32 %0, %1, %2;" : "=r"(r) : "f"(b), "f"(a));
    return r;
}
__device__ __forceinline__ void mma16816(float* c, const uint32_t* a,
                                         const uint32_t* b) {
    asm volatile(
        "mma.sync.aligned.m16n8k16.row.col.f32.f16.f16.f32 "
        "{%0,%1,%2,%3}, {%4,%5,%6,%7}, {%8,%9}, {%0,%1,%2,%3};"
        : "+f"(c[0]), "+f"(c[1]), "+f"(c[2]), "+f"(c[3])
        : "r"(a[0]), "r"(a[1]), "r"(a[2]), "r"(a[3]), "r"(b[0]), "r"(b[1]));
}
__device__ __forceinline__ uint32_t smaddr(const void* p) {
    return (uint32_t)__cvta_generic_to_shared(p);
}
__device__ __forceinline__ void cpa16(uint32_t dst_smem, const void* src) {
    asm volatile("cp.async.cg.shared.global [%0], [%1], 16;"
                 :: "r"(dst_smem), "l"(src) : "memory");
}
__device__ __forceinline__ void cpa_commit() {
    asm volatile("cp.async.commit_group;" ::: "memory");
}
__device__ __forceinline__ void cpa_wait0() {
    asm volatile("cp.async.wait_group 0;" ::: "memory");
}

// ---------------------------------------------------------------------------
// prep: merge core pairs into fp16 fragment-order words (m̂ = r2*64+o12).
// ---------------------------------------------------------------------------
__global__ void k_prep(const float* __restrict__ c0, const float* __restrict__ c1,
                       const float* __restrict__ c2, const float* __restrict__ c3) {
    int t = blockIdx.x * blockDim.x + threadIdx.x;  // 0..32767
    if (t < 16384) {
        int w2 = t & 3, lane = (t >> 2) & 31, ks = (t >> 7) & 3, mrb = t >> 9;
        int g = lane >> 2, t4 = lane & 3;
        int mhat = mrb * 16 + (w2 & 1) * 8 + g;
        int k0 = ks * 16 + ((w2 >> 1) & 1) * 8 + t4 * 2;
        int r2 = mhat >> 6, o12 = mhat & 63;
        int o1 = o12 >> 3, o2 = o12 & 7;
        float s[2];
#pragma unroll
        for (int d = 0; d < 2; ++d) {
            int k = k0 + d;
            int i1 = k >> 3, i2 = k & 7;
            float acc = 0.0f;
#pragma unroll
            for (int r1 = 0; r1 < 8; ++r1)
                acc += c0[(i1 * 8 + o1) * 8 + r1] *
                       c1[((r1 * 8 + i2) * 8 + o2) * 8 + r2];
            s[d] = acc;
        }
        g_A[t] = pack_h2(s[0], s[1]);
    } else {
        int u = t - 16384;
        int w = u & 3, lane = (u >> 2) & 31, nbp = (u >> 7) & 3, ks = u >> 9;
        int g = lane >> 2, t4 = lane & 3;
        int nb = nbp * 2 + (w >> 1);
        int n  = nb * 8 + g;
        int k0 = ks * 16 + (w & 1) * 8 + t4 * 2;
        int o3 = n >> 3, o4 = n & 7;
        float s[2];
#pragma unroll
        for (int d = 0; d < 2; ++d) {
            int k2v = k0 + d;
            int r2 = k2v >> 6, i3 = (k2v >> 3) & 7, i4 = k2v & 7;
            float acc = 0.0f;
#pragma unroll
            for (int r3 = 0; r3 < 8; ++r3)
                acc += c2[((r2 * 8 + i3) * 8 + o3) * 8 + r3] *
                       c3[(r3 * 8 + i4) * 8 + o4];
            s[d] = acc;
        }
        g_B[u] = pack_h2(s[0], s[1]);
    }
}

// ---------------------------------------------------------------------------
// fused kernel. 4 batch rows per CTA.
// SMEM words: sG01[0,16384) sG23[16384,32768) sRed[32768,49152)
//             sX[49152,51200) sxf(fp32, pitch 68)[51200,55552)
// ---------------------------------------------------------------------------
__global__ __launch_bounds__(512, 1) void k_fused(const float* __restrict__ x,
                                                  const float* __restrict__ bias,
                                                  float* __restrict__ out) {
    extern __shared__ uint32_t sm[];
    uint32_t* sG01 = sm;
    uint32_t* sG23 = sm + 16384;
    uint32_t* sRed = sm + 32768;             // 8 slots x 2048 words
    uint32_t* sX   = sm + 49152;             // 2048 words
    float*    sxf  = (float*)(sm + 51200);   // 64 rows x pitch 68
    const int tid = threadIdx.x;
    const int lane = tid & 31, w = tid >> 5;
    const int g = lane >> 2, t4 = lane & 3;
    const int c2 = w >> 3, nh = (w >> 2) & 1, r2p = w & 3;
    const int b0 = blockIdx.x * 4;

    // cp.async one x row (fp32, row-major) into padded staging
#define CPA_XROW(b_) do {                                                     \
        const float* srcX_ = x + (size_t)(b_) * 4096;                         \
        _Pragma("unroll")                                                     \
        for (int e = 0; e < 2; ++e) {                                         \
            int idx_ = tid * 2 + e;                                           \
            int row_ = idx_ >> 4, seg_ = idx_ & 15;                           \
            cpa16(smaddr(&sxf[row_ * 68 + seg_ * 4]),                         \
                  srcX_ + row_ * 64 + seg_ * 4);                              \
        }                                                                     \
        cpa_commit();                                                         \
    } while (0)
    // staging -> fragment-order fp16 sX (proven splitXT math; pitch 68)
#define CONVERT_X() do {                                                      \
        _Pragma("unroll")                                                     \
        for (int it = 0; it < 4; ++it) {                                      \
            int widx = it * 512 + tid;                                        \
            int ww = widx & 3, fl = (widx >> 2) & 31;                         \
            int nbp_ = (widx >> 7) & 3, ks_ = widx >> 9;                      \
            int fg = fl >> 2, ft4 = fl & 3;                                   \
            int nb_ = nbp_ * 2 + (ww >> 1);                                   \
            int i34_ = nb_ * 8 + fg;                                          \
            int k0_ = ks_ * 16 + (ww & 1) * 8 + ft4 * 2;                      \
            sX[widx] = pack_h2(sxf[k0_ * 68 + i34_],                          \
                               sxf[(k0_ + 1) * 68 + i34_]);                   \
        }                                                                     \
    } while (0)

    // ---- prologue ----
    {   // weights (one group)
        const uint4* srcA = (const uint4*)g_A;
        const uint4* srcB = (const uint4*)g_B;
#pragma unroll
        for (int p = 0; p < 8; ++p) {
            int j = tid + 512 * p;
            cpa16(smaddr(&sG01[j * 4]), &srcA[j]);
            cpa16(smaddr(&sG23[j * 4]), &srcB[j]);
        }
        cpa_commit();
    }
    CPA_XROW(b0);
    cpa_wait0();
    __syncthreads();
    CONVERT_X();
    __syncthreads();          // sX(row0) published; staging free
    CPA_XROW(b0 + 1);

    for (int r = 0; r < 4; ++r) {
        // ---------------- stage 1 (z stays in registers) ----------------
        float acc1[2][2][4][4];   // [r2i][mt][nb_rel][q]
#pragma unroll
        for (int a = 0; a < 2; ++a)
#pragma unroll
            for (int b_ = 0; b_ < 2; ++b_)
#pragma unroll
                for (int n_ = 0; n_ < 4; ++n_)
#pragma unroll
                    for (int q = 0; q < 4; ++q) acc1[a][b_][n_][q] = 0.0f;

#pragma unroll
        for (int ks = 0; ks < 4; ++ks) {
            uint4 AQ[2][2];
#pragma unroll
            for (int r2i = 0; r2i < 2; ++r2i)
#pragma unroll
                for (int mt = 0; mt < 2; ++mt) {
                    int mrb = (r2p * 2 + r2i) * 4 + c2 * 2 + mt;
                    AQ[r2i][mt] = *(const uint4*)&sG01[((mrb * 4 + ks) * 32 + lane) * 4];
                }
            uint4 BQ[2];
#pragma unroll
            for (int p = 0; p < 2; ++p)
                BQ[p] = *(const uint4*)&sX[((ks * 4 + nh * 2 + p) * 32 + lane) * 4];
#pragma unroll
            for (int r2i = 0; r2i < 2; ++r2i)
#pragma unroll
                for (int mt = 0; mt < 2; ++mt)
#pragma unroll
                    for (int p = 0; p < 2; ++p) {
                        mma16816(acc1[r2i][mt][2 * p],
                                 (const uint32_t*)&AQ[r2i][mt], &BQ[p].x);
                        mma16816(acc1[r2i][mt][2 * p + 1],
                                 (const uint32_t*)&AQ[r2i][mt], &BQ[p].z);
                    }
        }

        // pack acc1 -> stage2 A-fragments (R13 epilogue packing, in regs)
        uint4 A2[8];   // idx = r2i*4 + mt*2 + p
#pragma unroll
        for (int r2i = 0; r2i < 2; ++r2i)
#pragma unroll
            for (int mt = 0; mt < 2; ++mt)
#pragma unroll
                for (int p = 0; p < 2; ++p) {
                    const float* A0 = acc1[r2i][mt][2 * p];
                    const float* A1 = acc1[r2i][mt][2 * p + 1];
                    uint4 v;
                    v.x = pack_h2(A0[0], A0[1]);
                    v.y = pack_h2(A0[2], A0[3]);
                    v.z = pack_h2(A1[0], A1[1]);
                    v.w = pack_h2(A1[2], A1[3]);
                    A2[r2i * 4 + mt * 2 + p] = v;
                }

        // ---------------- stage 2 (B-only LDS, partial K) ----------------
        float acc2[2][8][4];
#pragma unroll
        for (int a = 0; a < 2; ++a)
#pragma unroll
            for (int b_ = 0; b_ < 8; ++b_)
#pragma unroll
                for (int q = 0; q < 4; ++q) acc2[a][b_][q] = 0.0f;

#pragma unroll
        for (int r2i = 0; r2i < 2; ++r2i)
#pragma unroll
            for (int p = 0; p < 2; ++p) {
                int ks2 = (r2p * 2 + r2i) * 4 + nh * 2 + p;
                uint4 BQ2[4];
#pragma unroll
                for (int nbp = 0; nbp < 4; ++nbp)
                    BQ2[nbp] = *(const uint4*)&sG23[((ks2 * 4 + nbp) * 32 + lane) * 4];
#pragma unroll
                for (int mt = 0; mt < 2; ++mt)
#pragma unroll
                    for (int nbp = 0; nbp < 4; ++nbp) {
                        const uint32_t* af =
                            (const uint32_t*)&A2[r2i * 4 + mt * 2 + p];
                        mma16816(acc2[mt][2 * nbp],     af, &BQ2[nbp].x);
                        mma16816(acc2[mt][2 * nbp + 1], af, &BQ2[nbp].z);
                    }
            }

        // ---------------- reduction: 8 partials per c2-group ----------------
#define STS_PART(slot_) do {                                                  \
        _Pragma("unroll")                                                     \
        for (int i = 0; i < 16; ++i) {                                        \
            uint4 v;                                                          \
            v.x = __float_as_uint(acc2[i >> 3][i & 7][0]);                    \
            v.y = __float_as_uint(acc2[i >> 3][i & 7][1]);                    \
            v.z = __float_as_uint(acc2[i >> 3][i & 7][2]);                    \
            v.w = __float_as_uint(acc2[i >> 3][i & 7][3]);                    \
            *(uint4*)&sRed[(size_t)(slot_) * 2048 + (i * 32 + lane) * 4] = v; \
        }                                                                     \
    } while (0)
#define LDS_ADD(slot_) do {                                                   \
        _Pragma("unroll")                                                     \
        for (int i = 0; i < 16; ++i) {                                        \
            uint4 v = *(const uint4*)&sRed[(size_t)(slot_) * 2048 +           \
                                           (i * 32 + lane) * 4];              \
            acc2[i >> 3][i & 7][0] += __uint_as_float(v.x);                   \
            acc2[i >> 3][i & 7][1] += __uint_as_float(v.y);                   \
            acc2[i >> 3][i & 7][2] += __uint_as_float(v.z);                   \
            acc2[i >> 3][i & 7][3] += __uint_as_float(v.w);                   \
        }                                                                     \
    } while (0)

        if (r2p >= 2) STS_PART(c2 * 4 + nh * 2 + (r2p - 2));
        __syncthreads();
        if (r2p < 2) {
            LDS_ADD(c2 * 4 + nh * 2 + r2p);
            if (!(nh == 0 && r2p == 0)) STS_PART(c2 * 4 + nh * 2 + r2p);
        }
        __syncthreads();
        if (nh == 0 && r2p == 0) {   // warps 0 and 8 finish rows [32c2, +32)
            LDS_ADD(c2 * 4 + 1);
            LDS_ADD(c2 * 4 + 2);
            LDS_ADD(c2 * 4 + 3);
            const int b = b0 + r;
#pragma unroll
            for (int mt = 0; mt < 2; ++mt)
#pragma unroll
                for (int nb = 0; nb < 8; ++nb) {
                    int col = nb * 8 + t4 * 2;
                    int o12a = c2 * 32 + mt * 16 + g;
                    float2 bva = __ldg((const float2*)&bias[o12a * 64 + col]);
                    float2 va;
                    va.x = acc2[mt][nb][0] + bva.x;
                    va.y = acc2[mt][nb][1] + bva.y;
                    *(float2*)&out[((size_t)b * 64 + o12a) * 64 + col] = va;
                    int o12b = o12a + 8;
                    float2 bvb = __ldg((const float2*)&bias[o12b * 64 + col]);
                    float2 vb;
                    vb.x = acc2[mt][nb][2] + bvb.x;
                    vb.y = acc2[mt][nb][3] + bvb.y;
                    *(float2*)&out[((size_t)b * 64 + o12b) * 64 + col] = vb;
                }
        }

        if (r < 3) {
            cpa_wait0();       // x row r+1 arrived in staging
            __syncthreads();   // sRed reads done; staging published
            CONVERT_X();       // sX <- row r+1
            __syncthreads();   // sX published; staging free
            if (r < 2) CPA_XROW(b0 + r + 2);
        }
#undef STS_PART
#undef LDS_ADD
    }
#undef CPA_XROW
#undef CONVERT_X
}

// ---------------------------------------------------------------------------
extern "C" void kernel_launch(void* const* d_in, const int* in_sizes, int n_in,
                              void* d_out, int out_size) {
    (void)in_sizes; (void)n_in; (void)out_size;
    const float* x    = (const float*)d_in[0];
    const float* c0   = (const float*)d_in[1];
    const float* c1   = (const float*)d_in[2];
    const float* c2   = (const float*)d_in[3];
    const float* c3   = (const float*)d_in[4];
    const float* bias = (const float*)d_in[5];
    float* out = (float*)d_out;

    cudaFuncSetAttribute(k_fused, cudaFuncAttributeMaxDynamicSharedMemorySize,
                         222208);

    k_prep<<<128, 256>>>(c0, c1, c2, c3);
    k_fused<<<1024, 512, 222208>>>(x, bias, out);  // z register-chained
}